// round 2
// baseline (speedup 1.0000x reference)
#include <cuda_runtime.h>
#include <cstdint>
#include <math.h>
#include <limits.h>

#define NB    512      // batch
#define NRBOX 18
#define DD    2048
#define NROBJ 16
#define KSEL  3
#define NCLS  174
#define NCAT  321
#define NCAND 8192               // NB * NROBJ
#define GUM_PLANE 4194304u       // NB * NCAND
#define ORI_OFF 0
#define FEA_OFF 1048576          // NB*DD
#define LAB_OFF 4194304          // NB*DD + NB*KSEL*DD

// ---------------- scratch (static device globals; no allocation) ----------------
__device__ float g_objmean[NB * DD];
__device__ int   g_sel[NB * KSEL];
__device__ int   g_slot[NB * KSEL];
__device__ float g_lam[NB];
__device__ int   g_hc[NB];

// ---------------- Threefry-2x32 (20 rounds), matches jax.random ----------------
__host__ __device__ __forceinline__ uint32_t tf_rotl(uint32_t v, int r) {
    return (v << r) | (v >> (32 - r));
}

__host__ __device__ __forceinline__ void tf2x32(uint32_t k0, uint32_t k1,
                                                uint32_t x0, uint32_t x1,
                                                uint32_t& o0, uint32_t& o1) {
    uint32_t k2 = k0 ^ k1 ^ 0x1BD11BDAu;
    x0 += k0; x1 += k1;
#define TFR(r) { x0 += x1; x1 = tf_rotl(x1, r); x1 ^= x0; }
    TFR(13) TFR(15) TFR(26) TFR(6)
    x0 += k1; x1 += k2 + 1u;
    TFR(17) TFR(29) TFR(16) TFR(24)
    x0 += k2; x1 += k0 + 2u;
    TFR(13) TFR(15) TFR(26) TFR(6)
    x0 += k0; x1 += k1 + 3u;
    TFR(17) TFR(29) TFR(16) TFR(24)
    x0 += k1; x1 += k2 + 4u;
    TFR(13) TFR(15) TFR(26) TFR(6)
    x0 += k2; x1 += k0 + 5u;
#undef TFR
    o0 = x0; o1 = x1;
}

// partitionable random_bits: one 32-bit word per flat index m (< 2^32): y0 ^ y1 of T(key,(0,m))
__device__ __forceinline__ uint32_t tf_bits(uint32_t kx, uint32_t ky, uint32_t m) {
    uint32_t y0, y1;
    tf2x32(kx, ky, 0u, m, y0, y1);
    return y0 ^ y1;
}

__device__ __forceinline__ float bits_to_unit(uint32_t b) {
    // bitcast((b>>9)|0x3f800000) - 1  -> [0,1)
    return __uint_as_float((b >> 9) | 0x3f800000u) - 1.0f;
}

__device__ __forceinline__ float gumbel_from_bits(uint32_t b) {
    float f = bits_to_unit(b);
    float u = fmaxf(f, 1.17549435e-38f);     // jax uniform(minval=tiny)
    return -logf(-logf(u));
}

// ---------------- kernel 1: means (float4-vectorized) ----------------
__global__ __launch_bounds__(256) void mean_kernel(const float* __restrict__ fea,
                                                   float* __restrict__ out) {
    const int i = blockIdx.x;
    const float4* base = (const float4*)(fea + (size_t)i * NRBOX * DD);
    float4* ocomp = (float4*)(out + ORI_OFF + (size_t)i * DD);
    float4* omean = (float4*)(g_objmean + (size_t)i * DD);
    const int DD4 = DD / 4;   // 512
#pragma unroll
    for (int it = 0; it < 2; it++) {
        int d = threadIdx.x + it * 256;
        float4 s18 = make_float4(0.f, 0.f, 0.f, 0.f);
        float4 s16 = make_float4(0.f, 0.f, 0.f, 0.f);
#pragma unroll
        for (int j = 0; j < NRBOX; j++) {
            float4 v = base[j * DD4 + d];
            s18.x += v.x; s18.y += v.y; s18.z += v.z; s18.w += v.w;
            if (j >= 2) { s16.x += v.x; s16.y += v.y; s16.z += v.z; s16.w += v.w; }
        }
        const float i18 = 1.0f / 18.0f, i16 = 1.0f / 16.0f;
        ocomp[d] = make_float4(s18.x * i18, s18.y * i18, s18.z * i18, s18.w * i18);
        omean[d] = make_float4(s16.x * i16, s16.y * i16, s16.z * i16, s16.w * i16);
    }
}

// ---------------- kernel 2: selection (gumbel-argmax) + lam/slots/has_cand ----------------
__global__ __launch_bounds__(256) void select_kernel(
    const float* __restrict__ cooc,
    const int*   __restrict__ obj_ind,
    const int*   __restrict__ obj_cat,
    const int*   __restrict__ labels,
    uint32_t r1x, uint32_t r1y,
    uint32_t r2x, uint32_t r2y,
    uint32_t ksx, uint32_t ksy)
{
    __shared__ float lw[NCAT];
    __shared__ float sv[KSEL][256];
    __shared__ int   si[KSEL][256];
    __shared__ int   sflag;

    const int i = blockIdx.x;
    const int tid = threadIdx.x;
    if (tid == 0) sflag = 0;

    const int lab = labels[i];
    for (int t = tid; t < NCAT; t += 256) {
        float w = cooc[lab * NCAT + t];
        lw[t] = (w > 0.0f) ? logf(w) : -INFINITY;
    }
    __syncthreads();

    float bv[KSEL] = {-INFINITY, -INFINITY, -INFINITY};
    int   bi[KSEL] = {INT_MAX, INT_MAX, INT_MAX};
    bool anyp = false;
    const uint32_t rowbase = (uint32_t)i * (uint32_t)NCAND;

    for (int c = tid; c < NCAND; c += 256) {
        int j = c >> 4;
        int cat = __ldg(&obj_cat[j * NRBOX + 2 + (c & 15)]);
        float L = (j == i) ? -INFINITY : lw[cat];
        if (L > -INFINITY) {
            anyp = true;
            uint32_t m = rowbase + (uint32_t)c;
#pragma unroll
            for (int k = 0; k < KSEL; k++) {
                uint32_t b = tf_bits(r1x, r1y, m + (uint32_t)k * GUM_PLANE);
                float v = L + gumbel_from_bits(b);
                if (v > bv[k]) { bv[k] = v; bi[k] = c; }   // strictly increasing c per thread -> first-max kept
            }
        }
    }
    if (anyp) sflag = 1;

#pragma unroll
    for (int k = 0; k < KSEL; k++) { sv[k][tid] = bv[k]; si[k][tid] = bi[k]; }
    __syncthreads();

    for (int s = 128; s > 0; s >>= 1) {
        if (tid < s) {
#pragma unroll
            for (int k = 0; k < KSEL; k++) {
                float v2 = sv[k][tid + s]; int i2 = si[k][tid + s];
                float v1 = sv[k][tid];     int i1 = si[k][tid];
                if (v2 > v1 || (v2 == v1 && i2 < i1)) { sv[k][tid] = v2; si[k][tid] = i2; }
            }
        }
        __syncthreads();
    }

    if (tid < KSEL) {
        int idx = si[tid][0];
        g_sel[i * KSEL + tid] = (idx == INT_MAX) ? 0 : idx;  // XLA argmax(all -inf) -> 0
        // slots: randint(0,16), span=16 power-of-2 -> lower_bits % 16, key = second split of r3
        uint32_t sb = tf_bits(ksx, ksy, (uint32_t)(i * KSEL + tid));
        g_slot[i * KSEL + tid] = (int)(sb & 15u);
    }
    if (tid == 0) {
        uint32_t lb = tf_bits(r2x, r2y, (uint32_t)i);
        float f = bits_to_unit(lb);      // uniform(0,1): max(0, f*1+0) = f
        g_lam[i] = f;
        bool anyind = false;
#pragma unroll
        for (int o = 0; o < NROBJ; o++) anyind |= (obj_ind[i * NRBOX + 2 + o] != 0);
        g_hc[i] = (sflag && anyind) ? 1 : 0;
    }
}

// ---------------- kernel 3: gather + mix (float4 on feature rows) ----------------
__global__ __launch_bounds__(256) void mix_kernel(const float* __restrict__ fea,
                                                  const int* __restrict__ labels,
                                                  float* __restrict__ out) {
    const int k = blockIdx.x;
    const int i = blockIdx.y;
    const int tid = threadIdx.x;

    const int sel  = g_sel[i * KSEL + k];
    const int bsel = sel >> 4;
    const int osel = sel & 15;
    const float lam = g_lam[i];
    const int slot = g_slot[i * KSEL + k];
    const bool hc = (g_hc[i] != 0);

    float4* fout = (float4*)(out + FEA_OFF + ((size_t)(i * KSEL + k)) * DD);
    const float4* own = (const float4*)(fea + ((size_t)(i * NRBOX + 2 + slot)) * DD);
    const float4* sfe = (const float4*)(fea + ((size_t)(bsel * NRBOX + 2 + osel)) * DD);
    const float4* fb  = (const float4*)(g_objmean + (size_t)i * DD);

    if (hc) {
        const float oml = 1.0f - lam;
#pragma unroll
        for (int it = 0; it < 2; it++) {
            int d = tid + it * 256;
            float4 a = own[d], b = sfe[d];
            fout[d] = make_float4(a.x * lam + b.x * oml,
                                  a.y * lam + b.y * oml,
                                  a.z * lam + b.z * oml,
                                  a.w * lam + b.w * oml);
        }
    } else {
#pragma unroll
        for (int it = 0; it < 2; it++) {
            int d = tid + it * 256;
            fout[d] = fb[d];
        }
    }

    float* lout = out + LAB_OFF + (size_t)(i * KSEL + k) * NCLS;
    const int li = labels[i];
    const int lb = labels[bsel];
    for (int t = tid; t < NCLS; t += 256) {
        float a = (t == li) ? 1.0f : 0.0f;
        if (hc) {
            float c2 = (t == lb) ? 1.0f : 0.0f;
            lout[t] = a * lam + c2 * (1.0f - lam);
        } else {
            lout[t] = a;
        }
    }
}

// ---------------- launcher ----------------
extern "C" void kernel_launch(void* const* d_in, const int* in_sizes, int n_in,
                              void* d_out, int out_size) {
    const float* obj_fea = (const float*)d_in[0];
    const float* cooc    = (const float*)d_in[1];
    const int*   obj_ind = (const int*)d_in[2];
    const int*   obj_cat = (const int*)d_in[3];
    const int*   labels  = (const int*)d_in[4];
    float* out = (float*)d_out;

    // key(42) = (0,42); partitionable split: r_i = T(key,(0,i)); slots key k2 = T(r3,(0,1))
    uint32_t r1x, r1y, r2x, r2y, r3x, r3y, ksx, ksy;
    tf2x32(0u, 42u, 0u, 0u, r1x, r1y);
    tf2x32(0u, 42u, 0u, 1u, r2x, r2y);
    tf2x32(0u, 42u, 0u, 2u, r3x, r3y);
    tf2x32(r3x, r3y, 0u, 1u, ksx, ksy);

    mean_kernel<<<NB, 256>>>(obj_fea, out);
    select_kernel<<<NB, 256>>>(cooc, obj_ind, obj_cat, labels,
                               r1x, r1y, r2x, r2y, ksx, ksy);
    mix_kernel<<<dim3(KSEL, NB), 256>>>(obj_fea, labels, out);
}

// round 3
// speedup vs baseline: 1.3872x; 1.3872x over previous
#include <cuda_runtime.h>
#include <cstdint>
#include <math.h>
#include <limits.h>

#define NB    512      // batch
#define NRBOX 18
#define DD    2048
#define NROBJ 16
#define KSEL  3
#define NCLS  174
#define NCAT  321
#define NCAND 8192               // NB * NROBJ
#define GUM_PLANE 4194304u       // NB * NCAND
#define ORI_OFF 0
#define FEA_OFF 1048576          // NB*DD
#define LAB_OFF 4194304          // NB*DD + NB*KSEL*DD

// ---------------- scratch (static device globals; no allocation) ----------------
__device__ float g_objmean[NB * DD];
__device__ int   g_sel[NB * KSEL];
__device__ int   g_slot[NB * KSEL];
__device__ float g_lam[NB];
__device__ int   g_hc[NB];

// ---------------- Threefry-2x32 (20 rounds), matches jax.random ----------------
__host__ __device__ __forceinline__ uint32_t tf_rotl(uint32_t v, int r) {
    return (v << r) | (v >> (32 - r));
}

__host__ __device__ __forceinline__ void tf2x32(uint32_t k0, uint32_t k1,
                                                uint32_t x0, uint32_t x1,
                                                uint32_t& o0, uint32_t& o1) {
    uint32_t k2 = k0 ^ k1 ^ 0x1BD11BDAu;
    x0 += k0; x1 += k1;
#define TFR(r) { x0 += x1; x1 = tf_rotl(x1, r); x1 ^= x0; }
    TFR(13) TFR(15) TFR(26) TFR(6)
    x0 += k1; x1 += k2 + 1u;
    TFR(17) TFR(29) TFR(16) TFR(24)
    x0 += k2; x1 += k0 + 2u;
    TFR(13) TFR(15) TFR(26) TFR(6)
    x0 += k0; x1 += k1 + 3u;
    TFR(17) TFR(29) TFR(16) TFR(24)
    x0 += k1; x1 += k2 + 4u;
    TFR(13) TFR(15) TFR(26) TFR(6)
    x0 += k2; x1 += k0 + 5u;
#undef TFR
    o0 = x0; o1 = x1;
}

// partitionable random_bits: word m -> y0 ^ y1 of T(key,(0,m))
__device__ __forceinline__ uint32_t tf_bits(uint32_t kx, uint32_t ky, uint32_t m) {
    uint32_t y0, y1;
    tf2x32(kx, ky, 0u, m, y0, y1);
    return y0 ^ y1;
}

__device__ __forceinline__ float bits_to_unit(uint32_t b) {
    return __uint_as_float((b >> 9) | 0x3f800000u) - 1.0f;
}

// e = -log(u), u = max(unit, tiny). argmin over e*(1/w) == argmax over L + gumbel.
__device__ __forceinline__ float exp_from_bits(uint32_t b) {
    float f = bits_to_unit(b);
    float u = fmaxf(f, 1.17549435e-38f);
    return -logf(u);
}

// ---------------- kernel 1: means (flat, float4) ----------------
__global__ __launch_bounds__(256) void mean_kernel(const float* __restrict__ fea,
                                                   float* __restrict__ out) {
    const int t = blockIdx.x * 256 + threadIdx.x;   // 0 .. 512*512-1
    const int i = t >> 9;
    const int d = t & 511;
    const float4* base = (const float4*)(fea + (size_t)i * NRBOX * DD);
    float4 s18 = make_float4(0.f, 0.f, 0.f, 0.f);
    float4 s16 = make_float4(0.f, 0.f, 0.f, 0.f);
#pragma unroll
    for (int j = 0; j < NRBOX; j++) {
        float4 v = base[j * 512 + d];
        s18.x += v.x; s18.y += v.y; s18.z += v.z; s18.w += v.w;
        if (j >= 2) { s16.x += v.x; s16.y += v.y; s16.z += v.z; s16.w += v.w; }
    }
    const float i18 = 1.0f / 18.0f, i16 = 1.0f / 16.0f;
    ((float4*)(out + ORI_OFF))[t] = make_float4(s18.x * i18, s18.y * i18, s18.z * i18, s18.w * i18);
    ((float4*)g_objmean)[t]       = make_float4(s16.x * i16, s16.y * i16, s16.z * i16, s16.w * i16);
}

// ---------------- kernel 2: selection via compaction + 1-log gumbel ----------------
__global__ __launch_bounds__(256) void select_kernel(
    const float* __restrict__ cooc,
    const int*   __restrict__ obj_ind,
    const int*   __restrict__ obj_cat,
    const int*   __restrict__ labels,
    uint32_t r1x, uint32_t r1y,
    uint32_t r2x, uint32_t r2y,
    uint32_t ksx, uint32_t ksy)
{
    __shared__ float    s_rw[NCAT];       // 1/w, or -1 sentinel if w<=0
    __shared__ uint32_t s_list[NCAND];    // packed: c | (cat<<13)
    __shared__ int      s_cnt;
    __shared__ float    sv[KSEL][256];
    __shared__ int      si[KSEL][256];

    const int i   = blockIdx.x;
    const int tid = threadIdx.x;
    const int lane = tid & 31;
    if (tid == 0) s_cnt = 0;

    const int lab = labels[i];
    for (int t = tid; t < NCAT; t += 256) {
        float w = cooc[lab * NCAT + t];
        s_rw[t] = (w > 0.0f) ? (1.0f / w) : -1.0f;
    }
    __syncthreads();

    // phase A: compact passing candidates (warp-aggregated append)
#pragma unroll 4
    for (int c = tid; c < NCAND; c += 256) {
        int j   = c >> 4;
        int cat = __ldg(&obj_cat[j * NRBOX + 2 + (c & 15)]);
        bool pass = (j != i) && (s_rw[cat] > 0.0f);
        unsigned mask = __ballot_sync(0xffffffffu, pass);
        int base = 0;
        if (lane == 0 && mask) base = atomicAdd(&s_cnt, __popc(mask));
        base = __shfl_sync(0xffffffffu, base, 0);
        if (pass) {
            int rank = __popc(mask & ((1u << lane) - 1u));
            s_list[base + rank] = (uint32_t)c | ((uint32_t)cat << 13);
        }
    }
    __syncthreads();
    const int nc = s_cnt;

    // phase B: hash only compacted entries; argmin of e * (1/w), tie -> smaller c
    float bv[KSEL] = {INFINITY, INFINITY, INFINITY};
    int   bi[KSEL] = {INT_MAX, INT_MAX, INT_MAX};
    const uint32_t rowbase = (uint32_t)i * (uint32_t)NCAND;

    for (int t = tid; t < nc; t += 256) {
        uint32_t p = s_list[t];
        int c   = (int)(p & 8191u);
        int cat = (int)(p >> 13);
        float rw = s_rw[cat];
        uint32_t m = rowbase + (uint32_t)c;
#pragma unroll
        for (int k = 0; k < KSEL; k++) {
            uint32_t b = tf_bits(r1x, r1y, m + (uint32_t)k * GUM_PLANE);
            float v = exp_from_bits(b) * rw;
            if (v < bv[k] || (v == bv[k] && c < bi[k])) { bv[k] = v; bi[k] = c; }
        }
    }

#pragma unroll
    for (int k = 0; k < KSEL; k++) { sv[k][tid] = bv[k]; si[k][tid] = bi[k]; }
    __syncthreads();

    for (int s = 128; s > 0; s >>= 1) {
        if (tid < s) {
#pragma unroll
            for (int k = 0; k < KSEL; k++) {
                float v2 = sv[k][tid + s]; int i2 = si[k][tid + s];
                float v1 = sv[k][tid];     int i1 = si[k][tid];
                if (v2 < v1 || (v2 == v1 && i2 < i1)) { sv[k][tid] = v2; si[k][tid] = i2; }
            }
        }
        __syncthreads();
    }

    if (tid < KSEL) {
        int idx = si[tid][0];
        g_sel[i * KSEL + tid] = (idx == INT_MAX) ? 0 : idx;
        uint32_t sb = tf_bits(ksx, ksy, (uint32_t)(i * KSEL + tid));
        g_slot[i * KSEL + tid] = (int)(sb & 15u);
    }
    if (tid == 0) {
        uint32_t lb = tf_bits(r2x, r2y, (uint32_t)i);
        g_lam[i] = bits_to_unit(lb);
        bool anyind = false;
#pragma unroll
        for (int o = 0; o < NROBJ; o++) anyind |= (obj_ind[i * NRBOX + 2 + o] != 0);
        g_hc[i] = (nc > 0 && anyind) ? 1 : 0;
    }
}

// ---------------- kernel 3: gather + mix (float4) ----------------
__global__ __launch_bounds__(256) void mix_kernel(const float* __restrict__ fea,
                                                  const int* __restrict__ labels,
                                                  float* __restrict__ out) {
    const int k = blockIdx.x;
    const int i = blockIdx.y;
    const int tid = threadIdx.x;

    const int sel  = g_sel[i * KSEL + k];
    const int bsel = sel >> 4;
    const int osel = sel & 15;
    const float lam = g_lam[i];
    const int slot = g_slot[i * KSEL + k];
    const bool hc = (g_hc[i] != 0);

    float4* fout = (float4*)(out + FEA_OFF + ((size_t)(i * KSEL + k)) * DD);
    const float4* own = (const float4*)(fea + ((size_t)(i * NRBOX + 2 + slot)) * DD);
    const float4* sfe = (const float4*)(fea + ((size_t)(bsel * NRBOX + 2 + osel)) * DD);
    const float4* fb  = (const float4*)(g_objmean + (size_t)i * DD);

    if (hc) {
        const float oml = 1.0f - lam;
#pragma unroll
        for (int it = 0; it < 2; it++) {
            int d = tid + it * 256;
            float4 a = own[d], b = sfe[d];
            fout[d] = make_float4(a.x * lam + b.x * oml,
                                  a.y * lam + b.y * oml,
                                  a.z * lam + b.z * oml,
                                  a.w * lam + b.w * oml);
        }
    } else {
#pragma unroll
        for (int it = 0; it < 2; it++) {
            int d = tid + it * 256;
            fout[d] = fb[d];
        }
    }

    float* lout = out + LAB_OFF + (size_t)(i * KSEL + k) * NCLS;
    const int li = labels[i];
    const int lb = labels[bsel];
    for (int t = tid; t < NCLS; t += 256) {
        float a = (t == li) ? 1.0f : 0.0f;
        if (hc) {
            float c2 = (t == lb) ? 1.0f : 0.0f;
            lout[t] = a * lam + c2 * (1.0f - lam);
        } else {
            lout[t] = a;
        }
    }
}

// ---------------- launcher ----------------
extern "C" void kernel_launch(void* const* d_in, const int* in_sizes, int n_in,
                              void* d_out, int out_size) {
    const float* obj_fea = (const float*)d_in[0];
    const float* cooc    = (const float*)d_in[1];
    const int*   obj_ind = (const int*)d_in[2];
    const int*   obj_cat = (const int*)d_in[3];
    const int*   labels  = (const int*)d_in[4];
    float* out = (float*)d_out;

    uint32_t r1x, r1y, r2x, r2y, r3x, r3y, ksx, ksy;
    tf2x32(0u, 42u, 0u, 0u, r1x, r1y);
    tf2x32(0u, 42u, 0u, 1u, r2x, r2y);
    tf2x32(0u, 42u, 0u, 2u, r3x, r3y);
    tf2x32(r3x, r3y, 0u, 1u, ksx, ksy);

    mean_kernel<<<NB * 2, 256>>>(obj_fea, out);
    select_kernel<<<NB, 256>>>(cooc, obj_ind, obj_cat, labels,
                               r1x, r1y, r2x, r2y, ksx, ksy);
    mix_kernel<<<dim3(KSEL, NB), 256>>>(obj_fea, labels, out);
}